// round 2
// baseline (speedup 1.0000x reference)
#include <cuda_runtime.h>

typedef unsigned long long u64;

// ---------------------------------------------------------------------------
// Packed fp32x2 helpers (sm_103a): 2 FMAs per instruction on the fma pipe.
// ---------------------------------------------------------------------------
__device__ __forceinline__ u64 ffma2(u64 a, u64 b, u64 c) {
    asm("fma.rn.f32x2 %0, %1, %2, %0;" : "+l"(c) : "l"(a), "l"(b));
    return c;
}

__device__ __forceinline__ u64 dup2(float x) {
    u64 r;
    unsigned xi = __float_as_uint(x);
    asm("mov.b64 %0, {%1, %1};" : "=l"(r) : "r"(xi));
    return r;
}

__device__ __forceinline__ float2 unpk(u64 v) {
    unsigned lo, hi;
    asm("mov.b64 {%0, %1}, %2;" : "=r"(lo), "=r"(hi) : "l"(v));
    return make_float2(__uint_as_float(lo), __uint_as_float(hi));
}

// ---------------------------------------------------------------------------
// Scratch (__device__ globals: no allocation allowed anywhere)
//   g_xg : per-layer gate preactivations [B*T=65536][4H=4096] (1.07 GB)
//   g_h  : hidden states for all t; reused layer1 -> layer2   (268 MB)
//   g_c  : cell state [128][1024]
// Row convention: row = b*512 + t (matches [B,T,*]).
// ---------------------------------------------------------------------------
__device__ float g_xg[268435456ULL];   // 65536 * 4096
__device__ float g_h [67108864ULL];    // 65536 * 1024
__device__ float g_c [131072];         // 128 * 1024

// Software grid barrier state (generation barrier; count self-resets)
__device__ unsigned g_bar_count = 0;
__device__ volatile unsigned g_bar_gen = 0;

__device__ __forceinline__ void grid_barrier(int nblocks) {
    __syncthreads();
    if (threadIdx.x == 0) {
        __threadfence();                      // release all prior writes
        unsigned my_gen = g_bar_gen;
        if (atomicAdd(&g_bar_count, 1) == (unsigned)(nblocks - 1)) {
            g_bar_count = 0;
            __threadfence();
            g_bar_gen = my_gen + 1;           // release
        } else {
            while (g_bar_gen == my_gen) { }   // spin on L2
            __threadfence();
        }
    }
    __syncthreads();
}

// ---------------------------------------------------------------------------
// Generic C[M,N] = A[M,K] @ W[N,K]^T + b1 (+ b2)
// BM=128, BN=64, BK=16, 256 threads, per-thread 8x4 tile via f32x2.
// Grid: (N/64, M/128). Requires K % 16 == 0.
// ---------------------------------------------------------------------------
__global__ void __launch_bounds__(256)
gemm_bias(const float* __restrict__ A, const float* __restrict__ W,
          const float* __restrict__ b1, const float* __restrict__ b2,
          float* __restrict__ C, int N, int K)
{
    __shared__ float As[16 * 128];   // [k][m]
    __shared__ float Ws[16 * 64];    // [k][n]

    const int tid = threadIdx.x;
    const size_t m0 = (size_t)blockIdx.y * 128;
    const int n0 = blockIdx.x * 64;
    const int tm0 = (tid >> 4) * 8;     // 0..120
    const int tn0 = (tid & 15) * 4;     // 0..60

    u64 acc[4][4];
#pragma unroll
    for (int i = 0; i < 4; i++)
#pragma unroll
        for (int j = 0; j < 4; j++) acc[i][j] = 0ULL;

    const int lm  = tid >> 2;        // 0..63
    const int lkq = (tid & 3) * 4;   // 0,4,8,12

    for (int k0 = 0; k0 < K; k0 += 16) {
#pragma unroll
        for (int p = 0; p < 2; p++) {
            int m = lm + p * 64;
            float4 v = *(const float4*)(A + (m0 + m) * (size_t)K + k0 + lkq);
            As[(lkq + 0) * 128 + m] = v.x;
            As[(lkq + 1) * 128 + m] = v.y;
            As[(lkq + 2) * 128 + m] = v.z;
            As[(lkq + 3) * 128 + m] = v.w;
        }
        {
            float4 v = *(const float4*)(W + (size_t)(n0 + lm) * K + k0 + lkq);
            Ws[(lkq + 0) * 64 + lm] = v.x;
            Ws[(lkq + 1) * 64 + lm] = v.y;
            Ws[(lkq + 2) * 64 + lm] = v.z;
            Ws[(lkq + 3) * 64 + lm] = v.w;
        }
        __syncthreads();

#pragma unroll
        for (int k = 0; k < 16; k++) {
            u64 a0 = *(const u64*)(As + k * 128 + tm0 + 0);
            u64 a1 = *(const u64*)(As + k * 128 + tm0 + 2);
            u64 a2 = *(const u64*)(As + k * 128 + tm0 + 4);
            u64 a3 = *(const u64*)(As + k * 128 + tm0 + 6);
            float4 w = *(const float4*)(Ws + k * 64 + tn0);
            u64 w0 = dup2(w.x), w1 = dup2(w.y), w2 = dup2(w.z), w3 = dup2(w.w);
            acc[0][0] = ffma2(a0, w0, acc[0][0]); acc[0][1] = ffma2(a0, w1, acc[0][1]);
            acc[0][2] = ffma2(a0, w2, acc[0][2]); acc[0][3] = ffma2(a0, w3, acc[0][3]);
            acc[1][0] = ffma2(a1, w0, acc[1][0]); acc[1][1] = ffma2(a1, w1, acc[1][1]);
            acc[1][2] = ffma2(a1, w2, acc[1][2]); acc[1][3] = ffma2(a1, w3, acc[1][3]);
            acc[2][0] = ffma2(a2, w0, acc[2][0]); acc[2][1] = ffma2(a2, w1, acc[2][1]);
            acc[2][2] = ffma2(a2, w2, acc[2][2]); acc[2][3] = ffma2(a2, w3, acc[2][3]);
            acc[3][0] = ffma2(a3, w0, acc[3][0]); acc[3][1] = ffma2(a3, w1, acc[3][1]);
            acc[3][2] = ffma2(a3, w2, acc[3][2]); acc[3][3] = ffma2(a3, w3, acc[3][3]);
        }
        __syncthreads();
    }

#pragma unroll
    for (int j = 0; j < 4; j++) {
        int col = n0 + tn0 + j;
        float bias = b1[col] + (b2 ? b2[col] : 0.0f);
#pragma unroll
        for (int i = 0; i < 4; i++) {
            float2 v = unpk(acc[i][j]);
            size_t r = m0 + tm0 + 2 * i;
            C[r * (size_t)N + col]       = v.x + bias;
            C[(r + 1) * (size_t)N + col] = v.y + bias;
        }
    }
}

// ---------------------------------------------------------------------------
// Persistent LSTM layer: 128 blocks x 256 threads, loops t = 0..511 with a
// software grid barrier per step. Block bk owns hidden units j0..j0+7 ->
// 32 permuted gate columns (c = q*8 + r -> W row j0 + r + q*1024).
// Per step: G[128b x 32c] = h_{t-1} @ Wslice^T (f32x2), fused gate update.
// ---------------------------------------------------------------------------
#define NBLK 128

__global__ void __launch_bounds__(256)
lstm_layer(const float* __restrict__ xg,   // [65536][4096], row = b*512+t
           float* __restrict__ hseq,       // [65536][1024], row = b*512+t
           float* __restrict__ cst,        // [128][1024]
           const float* __restrict__ W)    // [4096][1024]
{
    __shared__ float As[32 * 128];   // [k][b]
    __shared__ float Ws[32 * 32];    // [k][c]
    __shared__ float Gs[128 * 32];   // [b][c]

    const int tid = threadIdx.x;
    const int j0 = blockIdx.x * 8;
    const int tm0 = (tid >> 3) * 4;   // 0..124 (b, 4 rows)
    const int tn0 = (tid & 7) * 4;    // 0..28  (c, 4 cols)

    // Preload the W slice indices once (same every step)
    const int wc   = tid >> 3;              // 0..31
    const int wkq  = (tid & 7) * 4;         // 0..28
    const int wrow = j0 + (wc & 7) + (wc >> 3) * 1024;

    for (int t = 0; t < 512; t++) {
        u64 acc[2][4];
#pragma unroll
        for (int i = 0; i < 2; i++)
#pragma unroll
            for (int j = 0; j < 4; j++) acc[i][j] = 0ULL;

        if (t > 0) {
            for (int k0 = 0; k0 < 1024; k0 += 32) {
                // A tile: h_{t-1}, 128 b x 32 k  (4 float4 per thread)
#pragma unroll
                for (int p = 0; p < 4; p++) {
                    int idx = tid + p * 256;
                    int b   = idx >> 3;
                    int kq  = (idx & 7) * 4;
                    float4 v = *(const float4*)(hseq + ((size_t)b * 512 + (t - 1)) * 1024 + k0 + kq);
                    As[(kq + 0) * 128 + b] = v.x;
                    As[(kq + 1) * 128 + b] = v.y;
                    As[(kq + 2) * 128 + b] = v.z;
                    As[(kq + 3) * 128 + b] = v.w;
                }
                // W tile: 32 permuted rows x 32 k (1 float4 per thread)
                {
                    float4 v = *(const float4*)(W + (size_t)wrow * 1024 + k0 + wkq);
                    Ws[(wkq + 0) * 32 + wc] = v.x;
                    Ws[(wkq + 1) * 32 + wc] = v.y;
                    Ws[(wkq + 2) * 32 + wc] = v.z;
                    Ws[(wkq + 3) * 32 + wc] = v.w;
                }
                __syncthreads();

#pragma unroll
                for (int k = 0; k < 32; k++) {
                    u64 a0 = *(const u64*)(As + k * 128 + tm0 + 0);
                    u64 a1 = *(const u64*)(As + k * 128 + tm0 + 2);
                    float4 w = *(const float4*)(Ws + k * 32 + tn0);
                    u64 w0 = dup2(w.x), w1 = dup2(w.y), w2 = dup2(w.z), w3 = dup2(w.w);
                    acc[0][0] = ffma2(a0, w0, acc[0][0]);
                    acc[0][1] = ffma2(a0, w1, acc[0][1]);
                    acc[0][2] = ffma2(a0, w2, acc[0][2]);
                    acc[0][3] = ffma2(a0, w3, acc[0][3]);
                    acc[1][0] = ffma2(a1, w0, acc[1][0]);
                    acc[1][1] = ffma2(a1, w1, acc[1][1]);
                    acc[1][2] = ffma2(a1, w2, acc[1][2]);
                    acc[1][3] = ffma2(a1, w3, acc[1][3]);
                }
                __syncthreads();
            }
        }

        // spill GEMM tile to smem for the gate pass
#pragma unroll
        for (int i = 0; i < 2; i++)
#pragma unroll
            for (int j = 0; j < 4; j++) {
                float2 v = unpk(acc[i][j]);
                Gs[(tm0 + 2 * i) * 32 + tn0 + j]     = v.x;
                Gs[(tm0 + 2 * i + 1) * 32 + tn0 + j] = v.y;
            }
        __syncthreads();

        // fused gate / state update: 1024 (b, r) items, 4 per thread
#pragma unroll
        for (int p = 0; p < 4; p++) {
            int item = tid + p * 256;
            int b = item >> 3;
            int r = item & 7;
            int j = j0 + r;
            size_t row = (size_t)b * 512 + t;
            const float* xr = xg + row * 4096;
            float ipre = Gs[b * 32 + 0  + r] + xr[j];
            float fpre = Gs[b * 32 + 8  + r] + xr[j + 1024];
            float gpre = Gs[b * 32 + 16 + r] + xr[j + 2048];
            float opre = Gs[b * 32 + 24 + r] + xr[j + 3072];
            float ig = 1.0f / (1.0f + expf(-ipre));
            float fg = 1.0f / (1.0f + expf(-fpre));
            float gv = tanhf(gpre);
            float og = 1.0f / (1.0f + expf(-opre));
            float cp = (t > 0) ? cst[b * 1024 + j] : 0.0f;
            float cn = fg * cp + ig * gv;
            float hv = og * tanhf(cn);
            cst[b * 1024 + j] = cn;
            hseq[row * 1024 + j] = hv;
        }

        grid_barrier(NBLK);   // h(t) visible to all blocks before step t+1
    }
}

// ---------------------------------------------------------------------------
// 5 graph nodes total: xg0 GEMM -> layer0 (persistent) -> xg1 GEMM ->
// layer1 (persistent) -> FC GEMM. Graph-capturable, allocation-free.
// ---------------------------------------------------------------------------
extern "C" void kernel_launch(void* const* d_in, const int* in_sizes, int n_in,
                              void* d_out, int out_size)
{
    const float* input = (const float*)d_in[0];
    const float* W_ih0 = (const float*)d_in[1];
    const float* W_hh0 = (const float*)d_in[2];
    const float* b_ih0 = (const float*)d_in[3];
    const float* b_hh0 = (const float*)d_in[4];
    const float* W_ih1 = (const float*)d_in[5];
    const float* W_hh1 = (const float*)d_in[6];
    const float* b_ih1 = (const float*)d_in[7];
    const float* b_hh1 = (const float*)d_in[8];
    const float* W_fc  = (const float*)d_in[9];
    const float* b_fc  = (const float*)d_in[10];
    float* out = (float*)d_out;

    float *xg, *h, *c;
    cudaGetSymbolAddress((void**)&xg, g_xg);
    cudaGetSymbolAddress((void**)&h,  g_h);
    cudaGetSymbolAddress((void**)&c,  g_c);

    dim3 gx(4096 / 64, 65536 / 128);   // (64, 512)

    // Layer 0: xg0 = x @ W_ih0^T + b_ih0 + b_hh0   (K = 64)
    gemm_bias<<<gx, 256>>>(input, W_ih0, b_ih0, b_hh0, xg, 4096, 64);
    lstm_layer<<<NBLK, 256>>>(xg, h, c, W_hh0);

    // Layer 1: xg1 = h1 @ W_ih1^T + b_ih1 + b_hh1  (K = 1024)
    gemm_bias<<<gx, 256>>>(h, W_ih1, b_ih1, b_hh1, xg, 4096, 1024);
    lstm_layer<<<NBLK, 256>>>(xg, h, c, W_hh1);

    // FC: preds = h2 @ W_fc^T + b_fc   (N = 64, K = 1024)
    dim3 gf(1, 512);
    gemm_bias<<<gf, 256>>>(h, W_fc, b_fc, nullptr, out, 64, 1024);
}

// round 5
// speedup vs baseline: 3.2215x; 3.2215x over previous
#include <cuda_runtime.h>
#include <cuda_bf16.h>

typedef unsigned long long u64;
typedef unsigned int u32;

// ===========================================================================
// PTX helpers — ONLY family-portable instructions (valid on .target sm_103):
// mma.sync bf16 (HMMA), ldmatrix, cp.async. No tcgen05/TMEM (sm_103a-only,
// rejected by this toolchain's virtual arch).
// ===========================================================================
__device__ __forceinline__ u64 ffma2(u64 a, u64 b, u64 c) {
    asm("fma.rn.f32x2 %0, %1, %2, %0;" : "+l"(c) : "l"(a), "l"(b));
    return c;
}
__device__ __forceinline__ u64 dup2(float x) {
    u64 r; unsigned xi = __float_as_uint(x);
    asm("mov.b64 %0, {%1, %1};" : "=l"(r) : "r"(xi));
    return r;
}
__device__ __forceinline__ float2 unpk(u64 v) {
    unsigned lo, hi;
    asm("mov.b64 {%0, %1}, %2;" : "=r"(lo), "=r"(hi) : "l"(v));
    return make_float2(__uint_as_float(lo), __uint_as_float(hi));
}
__device__ __forceinline__ u32 smem_u32(const void* p) {
    u32 a;
    asm("{ .reg .u64 t; cvta.to.shared.u64 t, %1; cvt.u32.u64 %0, t; }" : "=r"(a) : "l"(p));
    return a;
}
__device__ __forceinline__ void ldsm4(u32 addr, u32 r[4]) {
    asm volatile("ldmatrix.sync.aligned.m8n8.x4.shared.b16 {%0,%1,%2,%3}, [%4];"
                 : "=r"(r[0]), "=r"(r[1]), "=r"(r[2]), "=r"(r[3]) : "r"(addr));
}
__device__ __forceinline__ void mma16816(float d[4], const u32 a[4], u32 b0, u32 b1) {
    asm volatile(
        "mma.sync.aligned.m16n8k16.row.col.f32.bf16.bf16.f32 "
        "{%0,%1,%2,%3}, {%4,%5,%6,%7}, {%8,%9}, {%0,%1,%2,%3};"
        : "+f"(d[0]), "+f"(d[1]), "+f"(d[2]), "+f"(d[3])
        : "r"(a[0]), "r"(a[1]), "r"(a[2]), "r"(a[3]), "r"(b0), "r"(b1));
}
#define CPASYNC(s, g) \
    asm volatile("cp.async.ca.shared.global [%0], [%1], 16;" :: "r"(s), "l"(g))
#define CPCOMMIT() asm volatile("cp.async.commit_group;" ::: "memory")
#define CPWAIT(n)  asm volatile("cp.async.wait_group %0;" :: "n"(n) : "memory")

// ===========================================================================
// Scratch (__device__ globals)
// ===========================================================================
__device__ float g_xg[268435456ULL];              // [65536][4096] fp32
__device__ float g_h [67108864ULL];               // [65536][1024] fp32
__device__ float g_c [131072];                    // [128][1024]
__device__ __nv_bfloat16 g_whh_hi[4194304];       // permuted W_hh hi [4096][1024]
__device__ __nv_bfloat16 g_whh_lo[4194304];
__device__ __nv_bfloat16 g_wih_hi[4194304];       // W_ih (plain) hi [4096][K]
__device__ __nv_bfloat16 g_wih_lo[4194304];
__device__ __nv_bfloat16 g_in_hi[4194304];        // input planes [65536][64]
__device__ __nv_bfloat16 g_in_lo[4194304];
__device__ __nv_bfloat16 g_hs_hi[67108864ULL];    // hseq planes [65536][1024]
__device__ __nv_bfloat16 g_hs_lo[67108864ULL];

__device__ unsigned g_bar_count = 0;
__device__ volatile unsigned g_bar_gen = 0;

__device__ __forceinline__ void grid_barrier(int nblocks) {
    __syncthreads();
    if (threadIdx.x == 0) {
        __threadfence();
        unsigned my_gen = g_bar_gen;
        if (atomicAdd(&g_bar_count, 1) == (unsigned)(nblocks - 1)) {
            g_bar_count = 0;
            __threadfence();
            g_bar_gen = my_gen + 1;
        } else {
            while (g_bar_gen == my_gen) { }
            __threadfence();
        }
    }
    __syncthreads();
}

// ===========================================================================
// split_plane: elementwise fp32 -> bf16 hi + bf16 lo (residual). 4 elems/thr.
// Grid MUST be nelems / 1024.
// ===========================================================================
__global__ void __launch_bounds__(256)
split_plane(const float* __restrict__ src, __nv_bfloat16* __restrict__ hi,
            __nv_bfloat16* __restrict__ lo)
{
    size_t i4 = (size_t)blockIdx.x * 256 + threadIdx.x;
    float4 v = ((const float4*)src)[i4];
    float xs[4] = {v.x, v.y, v.z, v.w};
    __nv_bfloat16 h[4], l[4];
#pragma unroll
    for (int e = 0; e < 4; e++) {
        h[e] = __float2bfloat16(xs[e]);
        l[e] = __float2bfloat16(xs[e] - __bfloat162float(h[e]));
    }
    __nv_bfloat162* hp = (__nv_bfloat162*)(hi + i4 * 4);
    __nv_bfloat162* lp = (__nv_bfloat162*)(lo + i4 * 4);
    hp[0] = __nv_bfloat162(h[0], h[1]); hp[1] = __nv_bfloat162(h[2], h[3]);
    lp[0] = __nv_bfloat162(l[0], l[1]); lp[1] = __nv_bfloat162(l[2], l[3]);
}

// ===========================================================================
// split_w: W_hh split + permute for 128-CTA recurrence.
// out row = cta*32 + q*8 + r  <-  W_hh row (cta*8 + r + q*1024), cta=0..127.
// ===========================================================================
__global__ void __launch_bounds__(256)
split_w(const float* __restrict__ W, __nv_bfloat16* __restrict__ hi,
        __nv_bfloat16* __restrict__ lo)
{
    int orow = blockIdx.x;
    int cta = orow >> 5, cc = orow & 31;
    int q = cc >> 3, r = cc & 7;
    int wrow = cta * 8 + r + q * 1024;
    float4 v = ((const float4*)(W + (size_t)wrow * 1024))[threadIdx.x];
    size_t o = (size_t)orow * 1024 + threadIdx.x * 4;
    float xs[4] = {v.x, v.y, v.z, v.w};
#pragma unroll
    for (int e = 0; e < 4; e++) {
        __nv_bfloat16 h = __float2bfloat16(xs[e]);
        hi[o + e] = h;
        lo[o + e] = __float2bfloat16(xs[e] - __bfloat162float(h));
    }
}

// ===========================================================================
// SIMT f32x2 GEMM (kept for the small FC): C[M,N] = A[M,K]@W[N,K]^T + b1(+b2)
// ===========================================================================
__global__ void __launch_bounds__(256)
gemm_bias(const float* __restrict__ A, const float* __restrict__ W,
          const float* __restrict__ b1, const float* __restrict__ b2,
          float* __restrict__ C, int N, int K)
{
    __shared__ float As[16 * 128];
    __shared__ float Ws[16 * 64];

    const int tid = threadIdx.x;
    const size_t m0 = (size_t)blockIdx.y * 128;
    const int n0 = blockIdx.x * 64;
    const int tm0 = (tid >> 4) * 8;
    const int tn0 = (tid & 15) * 4;

    u64 acc[4][4];
#pragma unroll
    for (int i = 0; i < 4; i++)
#pragma unroll
        for (int j = 0; j < 4; j++) acc[i][j] = 0ULL;

    const int lm  = tid >> 2;
    const int lkq = (tid & 3) * 4;

    for (int k0 = 0; k0 < K; k0 += 16) {
#pragma unroll
        for (int p = 0; p < 2; p++) {
            int m = lm + p * 64;
            float4 v = *(const float4*)(A + (m0 + m) * (size_t)K + k0 + lkq);
            As[(lkq + 0) * 128 + m] = v.x;
            As[(lkq + 1) * 128 + m] = v.y;
            As[(lkq + 2) * 128 + m] = v.z;
            As[(lkq + 3) * 128 + m] = v.w;
        }
        {
            float4 v = *(const float4*)(W + (size_t)(n0 + lm) * K + k0 + lkq);
            Ws[(lkq + 0) * 64 + lm] = v.x;
            Ws[(lkq + 1) * 64 + lm] = v.y;
            Ws[(lkq + 2) * 64 + lm] = v.z;
            Ws[(lkq + 3) * 64 + lm] = v.w;
        }
        __syncthreads();

#pragma unroll
        for (int k = 0; k < 16; k++) {
            u64 a0 = *(const u64*)(As + k * 128 + tm0 + 0);
            u64 a1 = *(const u64*)(As + k * 128 + tm0 + 2);
            u64 a2 = *(const u64*)(As + k * 128 + tm0 + 4);
            u64 a3 = *(const u64*)(As + k * 128 + tm0 + 6);
            float4 w = *(const float4*)(Ws + k * 64 + tn0);
            u64 w0 = dup2(w.x), w1 = dup2(w.y), w2 = dup2(w.z), w3 = dup2(w.w);
            acc[0][0] = ffma2(a0, w0, acc[0][0]); acc[0][1] = ffma2(a0, w1, acc[0][1]);
            acc[0][2] = ffma2(a0, w2, acc[0][2]); acc[0][3] = ffma2(a0, w3, acc[0][3]);
            acc[1][0] = ffma2(a1, w0, acc[1][0]); acc[1][1] = ffma2(a1, w1, acc[1][1]);
            acc[1][2] = ffma2(a1, w2, acc[1][2]); acc[1][3] = ffma2(a1, w3, acc[1][3]);
            acc[2][0] = ffma2(a2, w0, acc[2][0]); acc[2][1] = ffma2(a2, w1, acc[2][1]);
            acc[2][2] = ffma2(a2, w2, acc[2][2]); acc[2][3] = ffma2(a2, w3, acc[2][3]);
            acc[3][0] = ffma2(a3, w0, acc[3][0]); acc[3][1] = ffma2(a3, w1, acc[3][1]);
            acc[3][2] = ffma2(a3, w2, acc[3][2]); acc[3][3] = ffma2(a3, w3, acc[3][3]);
        }
        __syncthreads();
    }

#pragma unroll
    for (int j = 0; j < 4; j++) {
        int col = n0 + tn0 + j;
        float bias = b1[col] + (b2 ? b2[col] : 0.0f);
#pragma unroll
        for (int i = 0; i < 4; i++) {
            float2 v = unpk(acc[i][j]);
            size_t r = m0 + tm0 + 2 * i;
            C[r * (size_t)N + col]       = v.x + bias;
            C[(r + 1) * (size_t)N + col] = v.y + bias;
        }
    }
}

// ===========================================================================
// gemm_tc: C[M,N] = A[M,K]@W[N,K]^T + b1 + b2, bf16 hi/lo 3-pass via mma.sync.
// BM=128, BN=128, BK=64, 256 threads (8 warps, 2x4), grid (N/128, M/128).
// smem/buffer: Ahi,Alo,Whi,Wlo each [128][72] bf16 (pitch 144B); 2 buffers.
// ===========================================================================
#define GT_PITCH 144                     // bytes per smem row (72 bf16)
#define GT_PL    (128 * GT_PITCH)        // 18432 per plane
#define GT_BUF   (4 * GT_PL)             // 73728 per buffer
#define GT_SMEM  (2 * GT_BUF)            // 147456

__device__ __forceinline__ void gt_fill(u32 sb, const __nv_bfloat16* Ahi,
                                        const __nv_bfloat16* Alo,
                                        const __nv_bfloat16* Whi,
                                        const __nv_bfloat16* Wlo,
                                        size_t m0, int n0, int K, int k0, int tid)
{
#pragma unroll
    for (int i = 0; i < 8; i++) {        // A: 2 planes x 128 rows x 8 segs
        int idx = tid + i * 256;
        int pl = idx >> 10, r2 = idx & 1023;
        int rr = r2 >> 3, ks = r2 & 7;
        const __nv_bfloat16* src = (pl ? Alo : Ahi) + (m0 + rr) * (size_t)K + k0 + ks * 8;
        CPASYNC(sb + pl * GT_PL + rr * GT_PITCH + ks * 16, src);
    }
#pragma unroll
    for (int i = 0; i < 8; i++) {        // W
        int idx = tid + i * 256;
        int pl = idx >> 10, r2 = idx & 1023;
        int rr = r2 >> 3, ks = r2 & 7;
        const __nv_bfloat16* src = (pl ? Wlo : Whi) + (size_t)(n0 + rr) * K + k0 + ks * 8;
        CPASYNC(sb + 2 * GT_PL + pl * GT_PL + rr * GT_PITCH + ks * 16, src);
    }
}

__global__ void __launch_bounds__(256, 1)
gemm_tc(const __nv_bfloat16* __restrict__ Ahi, const __nv_bfloat16* __restrict__ Alo,
        const __nv_bfloat16* __restrict__ Whi, const __nv_bfloat16* __restrict__ Wlo,
        const float* __restrict__ b1, const float* __restrict__ b2,
        float* __restrict__ C, int N, int K)
{
    extern __shared__ char smem[];
    const u32 sbase = smem_u32(smem);
    const int tid = threadIdx.x;
    const int wid = tid >> 5, lane = tid & 31;
    const int wr = wid >> 2, wc = wid & 3;
    const size_t m0 = (size_t)blockIdx.y * 128;
    const int n0 = blockIdx.x * 128;
    const int NC = K / 64;

    float acc[4][4][4];                  // [mb][nb][4]
#pragma unroll
    for (int a = 0; a < 4; a++)
#pragma unroll
        for (int b = 0; b < 4; b++)
#pragma unroll
            for (int e = 0; e < 4; e++) acc[a][b][e] = 0.0f;

    // per-lane ldmatrix row/col components
    const u32 a_r  = (u32)(lane & 15);
    const u32 a_c8 = (u32)((lane >> 4) << 3);
    const u32 b_r  = (u32)(((lane >> 4) << 3) + (lane & 7));
    const u32 b_c8 = (u32)(((lane >> 3) & 1) << 3);

    gt_fill(sbase, Ahi, Alo, Whi, Wlo, m0, n0, K, 0, tid);
    CPCOMMIT();

    for (int c = 0; c < NC; c++) {
        if (c + 1 < NC) {
            gt_fill(sbase + ((c + 1) & 1) * GT_BUF, Ahi, Alo, Whi, Wlo,
                    m0, n0, K, (c + 1) * 64, tid);
            CPCOMMIT();
            CPWAIT(1);
        } else {
            CPWAIT(0);
        }
        __syncthreads();

        const u32 ab = sbase + (c & 1) * GT_BUF;
#pragma unroll
        for (int kk = 0; kk < 4; kk++) {
            const u32 kc = (u32)(kk * 16);
            // W frags: 32 n-rows, hi & lo
            u32 baddr = ab + 2 * GT_PL + (wc * 32 + b_r) * GT_PITCH + (kc + b_c8) * 2;
            u32 bh0[4], bh1[4], bl0[4], bl1[4];
            ldsm4(baddr, bh0);
            ldsm4(baddr + 16 * GT_PITCH, bh1);
            ldsm4(baddr + GT_PL, bl0);
            ldsm4(baddr + GT_PL + 16 * GT_PITCH, bl1);
#pragma unroll
            for (int mb = 0; mb < 4; mb++) {
                u32 aaddr = ab + (wr * 64 + mb * 16 + a_r) * GT_PITCH + (kc + a_c8) * 2;
                u32 ah[4], al[4];
                ldsm4(aaddr, ah);
                ldsm4(aaddr + GT_PL, al);
                mma16816(acc[mb][0], ah, bh0[0], bh0[1]);
                mma16816(acc[mb][1], ah, bh0[2], bh0[3]);
                mma16816(acc[mb][2], ah, bh1[0], bh1[1]);
                mma16816(acc[mb][3], ah, bh1[2], bh1[3]);
                mma16816(acc[mb][0], ah, bl0[0], bl0[1]);
                mma16816(acc[mb][1], ah, bl0[2], bl0[3]);
                mma16816(acc[mb][2], ah, bl1[0], bl1[1]);
                mma16816(acc[mb][3], ah, bl1[2], bl1[3]);
                mma16816(acc[mb][0], al, bh0[0], bh0[1]);
                mma16816(acc[mb][1], al, bh0[2], bh0[3]);
                mma16816(acc[mb][2], al, bh1[0], bh1[1]);
                mma16816(acc[mb][3], al, bh1[2], bh1[3]);
            }
        }
        __syncthreads();
    }

    // epilogue: bias + store
#pragma unroll
    for (int nb = 0; nb < 4; nb++) {
        int col = n0 + wc * 32 + nb * 8 + (lane & 3) * 2;
        float bs0 = b1[col]     + b2[col];
        float bs1 = b1[col + 1] + b2[col + 1];
#pragma unroll
        for (int mb = 0; mb < 4; mb++) {
            size_t row = m0 + wr * 64 + mb * 16 + (lane >> 2);
            float2 v0 = make_float2(acc[mb][nb][0] + bs0, acc[mb][nb][1] + bs1);
            float2 v1 = make_float2(acc[mb][nb][2] + bs0, acc[mb][nb][3] + bs1);
            *(float2*)(C + row * (size_t)N + col)       = v0;
            *(float2*)(C + (row + 8) * (size_t)N + col) = v1;
        }
    }
}

// ===========================================================================
// Persistent recurrence via mma.sync. 128 CTAs x 256 threads.
// CTA owns 8 hidden units -> M=32 permuted gate rows (q*8+r), N=128 batch,
// K=1024 in 16 chunks of 64 (cp.async double buffer). 3-pass bf16 hi/lo.
// smem/buffer: Ahi,Alo [32][72], Bhi,Blo [128][72]; 2 buffers; Gs [32][129]f32
// ===========================================================================
#define LS_PITCH 144
#define LS_APL   (32 * LS_PITCH)         // 4608
#define LS_BPL   (128 * LS_PITCH)        // 18432
#define LS_BUF   (2 * LS_APL + 2 * LS_BPL)   // 46080
#define LS_GS    (2 * LS_BUF)            // 92160
#define LS_SMEM  (LS_GS + 32 * 129 * 4)  // 108672
#define LSTM_NBLK 128

__device__ __forceinline__ void ls_fill(u32 sb, const __nv_bfloat16* Whi,
                                        const __nv_bfloat16* Wlo,
                                        const __nv_bfloat16* hhi,
                                        const __nv_bfloat16* hlo,
                                        int cta, int tp, int k0, int tid)
{
#pragma unroll
    for (int i = 0; i < 2; i++) {        // A (Wperm slice): 2 planes x 32 x 8
        int idx = tid + i * 256;
        int pl = idx >> 8, r2 = idx & 255;
        int rr = r2 >> 3, ks = r2 & 7;
        const __nv_bfloat16* src = (pl ? Wlo : Whi) +
            (size_t)(cta * 32 + rr) * 1024 + k0 + ks * 8;
        CPASYNC(sb + pl * LS_APL + rr * LS_PITCH + ks * 16, src);
    }
#pragma unroll
    for (int i = 0; i < 8; i++) {        // B (h planes): 2 planes x 128 x 8
        int idx = tid + i * 256;
        int pl = idx >> 10, r2 = idx & 1023;
        int rb = r2 >> 3, ks = r2 & 7;
        const __nv_bfloat16* src = (pl ? hlo : hhi) +
            ((size_t)rb * 512 + tp) * 1024 + k0 + ks * 8;
        CPASYNC(sb + 2 * LS_APL + pl * LS_BPL + rb * LS_PITCH + ks * 16, src);
    }
}

__global__ void __launch_bounds__(256, 1)
lstm_mma(const float* __restrict__ xg,          // [65536][4096]
         float* __restrict__ hseq,              // [65536][1024] fp32
         float* __restrict__ cst,               // [128][1024]
         const __nv_bfloat16* __restrict__ Whi, // permuted [4096][1024]
         const __nv_bfloat16* __restrict__ Wlo,
         __nv_bfloat16* __restrict__ hhi,       // hseq hi plane [65536][1024]
         __nv_bfloat16* __restrict__ hlo)
{
    extern __shared__ char smem[];
    const u32 sbase = smem_u32(smem);
    float* Gs = (float*)(smem + LS_GS);
    const int tid = threadIdx.x;
    const int wid = tid >> 5, lane = tid & 31;
    const int wr = wid >> 2, wc = wid & 3;
    const int cta = blockIdx.x;
    const int j0 = cta * 8;

    const u32 a_r  = (u32)(lane & 15);
    const u32 a_c8 = (u32)((lane >> 4) << 3);
    const u32 b_r  = (u32)(((lane >> 4) << 3) + (lane & 7));
    const u32 b_c8 = (u32)(((lane >> 3) & 1) << 3);

    const int bB = tid >> 1;             // gate-pass batch index
    const int half = tid & 1;            // unit half (0: units 0-3, 1: 4-7)

    for (int t = 0; t < 512; t++) {
        if (t > 0) {
            float acc[4][4];
#pragma unroll
            for (int b = 0; b < 4; b++)
#pragma unroll
                for (int e = 0; e < 4; e++) acc[b][e] = 0.0f;

            ls_fill(sbase, Whi, Wlo, hhi, hlo, cta, t - 1, 0, tid);
            CPCOMMIT();

            for (int c = 0; c < 16; c++) {
                if (c < 15) {
                    ls_fill(sbase + ((c + 1) & 1) * LS_BUF, Whi, Wlo, hhi, hlo,
                            cta, t - 1, (c + 1) * 64, tid);
                    CPCOMMIT();
                    CPWAIT(1);
                } else {
                    CPWAIT(0);
                }
                __syncthreads();

                const u32 ab = sbase + (c & 1) * LS_BUF;
#pragma unroll
                for (int kk = 0; kk < 4; kk++) {
                    const u32 kc = (u32)(kk * 16);
                    u32 aaddr = ab + (wr * 16 + a_r) * LS_PITCH + (kc + a_c8) * 2;
                    u32 ah[4], al[4];
                    ldsm4(aaddr, ah);
                    ldsm4(aaddr + LS_APL, al);
                    u32 baddr = ab + 2 * LS_APL + (wc * 32 + b_r) * LS_PITCH + (kc + b_c8) * 2;
                    u32 bh0[4], bh1[4], bl0[4], bl1[4];
                    ldsm4(baddr, bh0);
                    ldsm4(baddr + 16 * LS_PITCH, bh1);
                    ldsm4(baddr + LS_BPL, bl0);
                    ldsm4(baddr + LS_BPL + 16 * LS_PITCH, bl1);
                    mma16816(acc[0], ah, bh0[0], bh0[1]);
                    mma16816(acc[1], ah, bh0[2], bh0[3]);
                    mma16816(acc[2], ah, bh1[0], bh1[1]);
                    mma16816(acc[3], ah, bh1[2], bh1[3]);
                    mma16816(acc[0], ah, bl0[0], bl0[1]);
                    mma16816(acc[1], ah, bl0[2], bl0[3]);
                    mma16816(acc[2], ah, bl1[0], bl1[1]);
                    mma16816(acc[3], ah, bl1[2], bl1[3]);
                    mma16816(acc[0], al, bh0[0], bh0[1]);
                    mma16816(acc[1], al, bh0[2], bh0[3]);
                    mma16816(acc[2], al, bh1[0], bh1[1]);
                    mma16816(acc[3], al, bh1[2], bh1[3]);
                }
                __syncthreads();
            }

            // spill accum to Gs[32 gate rows][128 batch] (pitch 129)
#pragma unroll
            for (int nb = 0; nb < 4; nb++) {
                int n = wc * 32 + nb * 8 + (lane & 3) * 2;
                int m = wr * 16 + (lane >> 2);
                Gs[m * 129 + n]           = acc[nb][0];
                Gs[m * 129 + n + 1]       = acc[nb][1];
                Gs[(m + 8) * 129 + n]     = acc[nb][2];
                Gs[(m + 8) * 129 + n + 1] = acc[nb][3];
            }
            __syncthreads();
        }

        // fused gate pass: thread = (batch bB, unit half). 4 units x 4 gates.
        {
            size_t row = (size_t)bB * 512 + t;
            const float* xr = xg + row * 4096 + j0 + half * 4;
            float4 xi = *(const float4*)(xr);
            float4 xf = *(const float4*)(xr + 1024);
            float4 xq = *(const float4*)(xr + 2048);
            float4 xo = *(const float4*)(xr + 3072);
            float xia[4] = {xi.x, xi.y, xi.z, xi.w};
            float xfa[4] = {xf.x, xf.y, xf.z, xf.w};
            float xqa[4] = {xq.x, xq.y, xq.z, xq.w};
            float xoa[4] = {xo.x, xo.y, xo.z, xo.w};
            float cpa[4] = {0.f, 0.f, 0.f, 0.f};
            float ria[4] = {0.f, 0.f, 0.f, 0.f};
            float rfa[4] = {0.f, 0.f, 0.f, 0.f};
            float rqa[4] = {0.f, 0.f, 0.f, 0.f};
            float roa[4] = {0.f, 0.f, 0.f, 0.f};
            if (t > 0) {
                float4 cv = *(const float4*)(cst + bB * 1024 + j0 + half * 4);
                cpa[0] = cv.x; cpa[1] = cv.y; cpa[2] = cv.z; cpa[3] = cv.w;
#pragma unroll
                for (int r = 0; r < 4; r++) {
                    int u = half * 4 + r;
                    ria[r] = Gs[(0  + u) * 129 + bB];
                    rfa[r] = Gs[(8  + u) * 129 + bB];
                    rqa[r] = Gs[(16 + u) * 129 + bB];
                    roa[r] = Gs[(24 + u) * 129 + bB];
                }
            }
            float hva[4], cna[4];
#pragma unroll
            for (int r = 0; r < 4; r++) {
                float ig = 1.0f / (1.0f + expf(-(ria[r] + xia[r])));
                float fg = 1.0f / (1.0f + expf(-(rfa[r] + xfa[r])));
                float gv = tanhf(rqa[r] + xqa[r]);
                float og = 1.0f / (1.0f + expf(-(roa[r] + xoa[r])));
                cna[r] = fg * cpa[r] + ig * gv;
                hva[r] = og * tanhf(cna[r]);
            }
            *(float4*)(cst + bB * 1024 + j0 + half * 4) =
                make_float4(cna[0], cna[1], cna[2], cna[3]);
            *(float4*)(hseq + row * 1024 + j0 + half * 4) =
                make_float4(hva[0], hva[1], hva[2], hva[3]);
            __nv_bfloat16 hb[4], lb[4];
#pragma unroll
            for (int r = 0; r < 4; r++) {
                hb[r] = __float2bfloat16(hva[r]);
                lb[r] = __float2bfloat16(hva[r] - __bfloat162float(hb[r]));
            }
            __nv_bfloat162* hp = (__nv_bfloat162*)(hhi + row * 1024 + j0 + half * 4);
            __nv_bfloat162* lp = (__nv_bfloat162*)(hlo + row * 1024 + j0 + half * 4);
            hp[0] = __nv_bfloat162(hb[0], hb[1]); hp[1] = __nv_bfloat162(hb[2], hb[3]);
            lp[0] = __nv_bfloat162(lb[0], lb[1]); lp[1] = __nv_bfloat162(lb[2], lb[3]);
        }

        grid_barrier(LSTM_NBLK);
    }
}

// ===========================================================================
// Launch sequence (10 nodes), graph-capturable, allocation-free.
// ===========================================================================
extern "C" void kernel_launch(void* const* d_in, const int* in_sizes, int n_in,
                              void* d_out, int out_size)
{
    const float* input = (const float*)d_in[0];
    const float* W_ih0 = (const float*)d_in[1];
    const float* W_hh0 = (const float*)d_in[2];
    const float* b_ih0 = (const float*)d_in[3];
    const float* b_hh0 = (const float*)d_in[4];
    const float* W_ih1 = (const float*)d_in[5];
    const float* W_hh1 = (const float*)d_in[6];
    const float* b_ih1 = (const float*)d_in[7];
    const float* b_hh1 = (const float*)d_in[8];
    const float* W_fc  = (const float*)d_in[9];
    const float* b_fc  = (const float*)d_in[10];
    float* out = (float*)d_out;

    float *xg, *h, *c;
    __nv_bfloat16 *whhhi, *whhlo, *wihhi, *wihlo, *inhi, *inlo, *hshi, *hslo;
    cudaGetSymbolAddress((void**)&xg,    g_xg);
    cudaGetSymbolAddress((void**)&h,     g_h);
    cudaGetSymbolAddress((void**)&c,     g_c);
    cudaGetSymbolAddress((void**)&whhhi, g_whh_hi);
    cudaGetSymbolAddress((void**)&whhlo, g_whh_lo);
    cudaGetSymbolAddress((void**)&wihhi, g_wih_hi);
    cudaGetSymbolAddress((void**)&wihlo, g_wih_lo);
    cudaGetSymbolAddress((void**)&inhi,  g_in_hi);
    cudaGetSymbolAddress((void**)&inlo,  g_in_lo);
    cudaGetSymbolAddress((void**)&hshi,  g_hs_hi);
    cudaGetSymbolAddress((void**)&hslo,  g_hs_lo);

    cudaFuncSetAttribute(gemm_tc,  cudaFuncAttributeMaxDynamicSharedMemorySize, GT_SMEM);
    cudaFuncSetAttribute(lstm_mma, cudaFuncAttributeMaxDynamicSharedMemorySize, LS_SMEM);

    // ---- Layer 0 ----
    split_plane<<<4096, 256>>>(input, inhi, inlo);          // 65536*64 /1024
    split_plane<<<256, 256>>>(W_ih0, wihhi, wihlo);         // 4096*64  /1024
    {
        dim3 g(4096 / 128, 65536 / 128);                    // (32, 512)
        gemm_tc<<<g, 256, GT_SMEM>>>(inhi, inlo, wihhi, wihlo,
                                     b_ih0, b_hh0, xg, 4096, 64);
    }
    split_w<<<4096, 256>>>(W_hh0, whhhi, whhlo);
    lstm_mma<<<LSTM_NBLK, 256, LS_SMEM>>>(xg, h, c, whhhi, whhlo, hshi, hslo);

    // ---- Layer 1 ----
    split_plane<<<4096, 256>>>(W_ih1, wihhi, wihlo);        // 4096*1024 /1024  (BUGFIX: was 16384)
    {
        dim3 g(4096 / 128, 65536 / 128);
        gemm_tc<<<g, 256, GT_SMEM>>>(hshi, hslo, wihhi, wihlo,
                                     b_ih1, b_hh1, xg, 4096, 1024);
    }
    split_w<<<4096, 256>>>(W_hh1, whhhi, whhlo);
    lstm_mma<<<LSTM_NBLK, 256, LS_SMEM>>>(xg, h, c, whhhi, whhlo, hshi, hslo);

    // ---- FC (SIMT) ----
    dim3 gf(1, 512);
    gemm_bias<<<gf, 256>>>(h, W_fc, b_fc, nullptr, out, 64, 1024);
}